// round 4
// baseline (speedup 1.0000x reference)
#include <cuda_runtime.h>

// Problem constants (fixed-shape problem)
#define B_DIM 128
#define K_DIM 2048
#define D_DIM 512

// Tiling for the main fused dual-GEMM kernel
#define BM 64          // batch rows per block
#define BN 16          // k columns per block
#define DT 64          // depth chunk

// Scratch for per-row stats (no cudaMalloc allowed)
__device__ float g_uu[K_DIM];   // ||p_k||^2  (== ||u_k||^2)
__device__ float g_ua[K_DIM];   // <u_k, a_k> = -<p_k, a_k>
__device__ float g_a2[K_DIM];   // ||a_k||^2
__device__ float g_vv[B_DIM];   // ||x_b||^2

// ---------------------------------------------------------------------------
// Kernel 1: per-k stats (uu, ua, a2) and per-b stats (vv).
// One warp per row. Tasks: [0, K) -> k rows, [K, K+B) -> b rows.
// ---------------------------------------------------------------------------
__global__ void stats_kernel(const float* __restrict__ inp,
                             const float* __restrict__ p,
                             const float* __restrict__ a) {
    int warp = (blockIdx.x * blockDim.x + threadIdx.x) >> 5;
    int lane = threadIdx.x & 31;

    if (warp < K_DIM) {
        const float4* pr = (const float4*)(p + warp * D_DIM);
        const float4* ar = (const float4*)(a + warp * D_DIM);
        float pp = 0.f, pa = 0.f, aa = 0.f;
#pragma unroll
        for (int i = 0; i < D_DIM / 128; i++) {          // 4 iterations of float4
            float4 pv = pr[lane + i * 32];
            float4 av = ar[lane + i * 32];
            pp += pv.x * pv.x + pv.y * pv.y + pv.z * pv.z + pv.w * pv.w;
            pa += pv.x * av.x + pv.y * av.y + pv.z * av.z + pv.w * av.w;
            aa += av.x * av.x + av.y * av.y + av.z * av.z + av.w * av.w;
        }
#pragma unroll
        for (int off = 16; off > 0; off >>= 1) {
            pp += __shfl_xor_sync(0xFFFFFFFFu, pp, off);
            pa += __shfl_xor_sync(0xFFFFFFFFu, pa, off);
            aa += __shfl_xor_sync(0xFFFFFFFFu, aa, off);
        }
        if (lane == 0) {
            g_uu[warp] = pp;
            g_ua[warp] = -pa;
            g_a2[warp] = aa;
        }
    } else if (warp < K_DIM + B_DIM) {
        int b = warp - K_DIM;
        const float4* xr = (const float4*)(inp + b * D_DIM);
        float vv = 0.f;
#pragma unroll
        for (int i = 0; i < D_DIM / 128; i++) {
            float4 xv = xr[lane + i * 32];
            vv += xv.x * xv.x + xv.y * xv.y + xv.z * xv.z + xv.w * xv.w;
        }
#pragma unroll
        for (int off = 16; off > 0; off >>= 1)
            vv += __shfl_xor_sync(0xFFFFFFFFu, vv, off);
        if (lane == 0) g_vv[b] = vv;
    }
}

// ---------------------------------------------------------------------------
// Kernel 2: fused dual GEMM (x @ p^T, x @ a^T) + hyperbolic MLR epilogue.
// Grid: (K/BN, B/BM). Block: 256 threads. Each thread: 4 b's x 1 k, two accs
// per output (xp, xa). Epilogue applies the Ganea logit formula directly.
// ---------------------------------------------------------------------------
__global__ __launch_bounds__(256, 2)
void hyper_logits_kernel(const float* __restrict__ inp,
                         const float* __restrict__ p,
                         const float* __restrict__ a,
                         float* __restrict__ out) {
    // xs rows padded to 68 floats (272B = 17*16B) -> float4-aligned rows,
    // store-phase bank stride 68 mod 32 = 4 (4-way, acceptable).
    __shared__ __align__(16) float xs[DT][BM + 4];
    __shared__ float ps[BN][DT + 1];
    __shared__ float as_[BN][DT + 1];

    const int tid = threadIdx.x;
    const int kl = tid & (BN - 1);       // 0..15 : local k
    const int bg = tid >> 4;             // 0..15 : group of 4 b's
    const int kbase = blockIdx.x * BN;
    const int bbase = blockIdx.y * BM;

    float accp0 = 0.f, accp1 = 0.f, accp2 = 0.f, accp3 = 0.f;
    float acca0 = 0.f, acca1 = 0.f, acca2 = 0.f, acca3 = 0.f;

    for (int d0 = 0; d0 < D_DIM; d0 += DT) {
        // inp chunk [BM x DT] stored transposed: xs[d][b]
#pragma unroll
        for (int i = 0; i < (BM * DT) / 256; i++) {      // 16 iters
            int idx = tid + i * 256;
            int dd = idx & (DT - 1);
            int bb = idx >> 6;
            xs[dd][bb] = inp[(bbase + bb) * D_DIM + d0 + dd];
        }
        // p, a chunks [BN x DT]
#pragma unroll
        for (int i = 0; i < (BN * DT) / 256; i++) {      // 4 iters
            int idx = tid + i * 256;
            int dd = idx & (DT - 1);
            int kk = idx >> 6;
            ps[kk][dd]  = p[(kbase + kk) * D_DIM + d0 + dd];
            as_[kk][dd] = a[(kbase + kk) * D_DIM + d0 + dd];
        }
        __syncthreads();

#pragma unroll
        for (int d = 0; d < DT; d++) {
            float4 xv = *(const float4*)&xs[d][bg * 4];
            float pv = ps[kl][d];
            float av = as_[kl][d];
            accp0 += xv.x * pv; accp1 += xv.y * pv;
            accp2 += xv.z * pv; accp3 += xv.w * pv;
            acca0 += xv.x * av; acca1 += xv.y * av;
            acca2 += xv.z * av; acca3 += xv.w * av;
        }
        __syncthreads();
    }

    // ---- Epilogue (c = 1, sqrt(c) = 1) ----
    const int k = kbase + kl;
    const float uu = g_uu[k];
    const float ua = g_ua[k];
    const float anorm = sqrtf(g_a2[k]);
    const float lam = 2.0f / (1.0f - uu);     // conformal factor at p_k
    const float coef = lam * anorm;           // (lam * ||a|| / sc), sc = 1
    const float beta = 1.0f - uu;             // 1 - c*uu

    float xp[4] = {accp0, accp1, accp2, accp3};
    float xa[4] = {acca0, acca1, acca2, acca3};

#pragma unroll
    for (int i = 0; i < 4; i++) {
        int b = bbase + bg * 4 + i;
        float vv = g_vv[b];
        float uv = -xp[i];                               // <u, x> = -<p, x>
        float alpha = 1.0f + 2.0f * uv + vv;             // 1 + 2c*uv + c*vv
        float den   = 1.0f + 2.0f * uv + uu * vv;        // 1 + 2c*uv + c^2*uu*vv
        float inv_den = 1.0f / den;
        float wa = (alpha * ua + beta * xa[i]) * inv_den;
        float ww = (alpha * alpha * uu + 2.0f * alpha * beta * uv
                    + beta * beta * vv) * (inv_den * inv_den);
        float num   = 2.0f * wa;                          // 2*sc*wa
        float denom = anorm * (1.0f - ww);                // ||a||*(1 - c*ww)
        out[b * K_DIM + k] = coef * asinhf(num / denom);
    }
}

// ---------------------------------------------------------------------------
extern "C" void kernel_launch(void* const* d_in, const int* in_sizes, int n_in,
                              void* d_out, int out_size) {
    const float* inp = (const float*)d_in[0];   // [B, D]
    const float* p   = (const float*)d_in[1];   // [K, D]
    const float* a   = (const float*)d_in[2];   // [K, D]
    float* out = (float*)d_out;                 // [B, K]

    // Kernel 1: (K + B) warps = 2176 warps -> 272 blocks of 256 threads
    int nwarps = K_DIM + B_DIM;
    int blocks1 = (nwarps * 32 + 255) / 256;
    stats_kernel<<<blocks1, 256>>>(inp, p, a);

    // Kernel 2: fused dual-GEMM + epilogue
    dim3 grid(K_DIM / BN, B_DIM / BM);   // (128, 2)
    hyper_logits_kernel<<<grid, 256>>>(inp, p, a, out);
}

// round 5
// speedup vs baseline: 1.2279x; 1.2279x over previous
#include <cuda_runtime.h>

// Problem constants (fixed-shape problem)
#define B_DIM 128
#define K_DIM 2048
#define D_DIM 512

// Tiling
#define BM 32            // batch rows per block
#define BN 32            // k columns per block
#define DT 32            // depth chunk per pipeline stage
#define DTP (DT + 4)     // padded row (36 floats = 144B, 16B-aligned)
#define THREADS 128
#define NSTAGE (D_DIM / DT)   // 16

// Scratch for per-row stats (no cudaMalloc allowed)
__device__ float g_uu[K_DIM];   // ||p_k||^2
__device__ float g_ua[K_DIM];   // <u_k, a_k> = -<p_k, a_k>
__device__ float g_a2[K_DIM];   // ||a_k||^2
__device__ float g_vv[B_DIM];   // ||x_b||^2

// ---------------------------------------------------------------------------
// Kernel 1: per-k stats (uu, ua, a2) and per-b stats (vv). One warp per row.
// ---------------------------------------------------------------------------
__global__ void stats_kernel(const float* __restrict__ inp,
                             const float* __restrict__ p,
                             const float* __restrict__ a) {
    int warp = (blockIdx.x * blockDim.x + threadIdx.x) >> 5;
    int lane = threadIdx.x & 31;

    if (warp < K_DIM) {
        const float4* pr = (const float4*)(p + warp * D_DIM);
        const float4* ar = (const float4*)(a + warp * D_DIM);
        float pp = 0.f, pa = 0.f, aa = 0.f;
#pragma unroll
        for (int i = 0; i < D_DIM / 128; i++) {
            float4 pv = pr[lane + i * 32];
            float4 av = ar[lane + i * 32];
            pp += pv.x * pv.x + pv.y * pv.y + pv.z * pv.z + pv.w * pv.w;
            pa += pv.x * av.x + pv.y * av.y + pv.z * av.z + pv.w * av.w;
            aa += av.x * av.x + av.y * av.y + av.z * av.z + av.w * av.w;
        }
#pragma unroll
        for (int off = 16; off > 0; off >>= 1) {
            pp += __shfl_xor_sync(0xFFFFFFFFu, pp, off);
            pa += __shfl_xor_sync(0xFFFFFFFFu, pa, off);
            aa += __shfl_xor_sync(0xFFFFFFFFu, aa, off);
        }
        if (lane == 0) {
            g_uu[warp] = pp;
            g_ua[warp] = -pa;
            g_a2[warp] = aa;
        }
    } else if (warp < K_DIM + B_DIM) {
        int b = warp - K_DIM;
        const float4* xr = (const float4*)(inp + b * D_DIM);
        float vv = 0.f;
#pragma unroll
        for (int i = 0; i < D_DIM / 128; i++) {
            float4 xv = xr[lane + i * 32];
            vv += xv.x * xv.x + xv.y * xv.y + xv.z * xv.z + xv.w * xv.w;
        }
#pragma unroll
        for (int off = 16; off > 0; off >>= 1)
            vv += __shfl_xor_sync(0xFFFFFFFFu, vv, off);
        if (lane == 0) g_vv[b] = vv;
    }
}

// ---------------------------------------------------------------------------
// cp.async helper: 16B global -> shared (L2-only caching, streamed data)
// ---------------------------------------------------------------------------
__device__ __forceinline__ void cp16(void* dst, const void* src) {
    unsigned saddr = (unsigned)__cvta_generic_to_shared(dst);
    asm volatile("cp.async.cg.shared.global [%0], [%1], 16;\n"
                 :: "r"(saddr), "l"(src));
}
__device__ __forceinline__ void cp_commit() {
    asm volatile("cp.async.commit_group;\n" ::: "memory");
}
__device__ __forceinline__ void cp_wait1() {
    asm volatile("cp.async.wait_group 1;\n" ::: "memory");
}
__device__ __forceinline__ void cp_wait0() {
    asm volatile("cp.async.wait_group 0;\n" ::: "memory");
}

// ---------------------------------------------------------------------------
// Kernel 2: fused dual GEMM (x @ p^T, x @ a^T) + hyperbolic MLR epilogue.
// Grid: (K/BN, B/BM) = (64, 4). Block: 128 threads.
// Thread tile: 4 b's x 2 k's (k and k+16), dual accumulators (p, a) = 16 outs.
// 2-stage cp.async pipeline over D in chunks of DT=32.
// ---------------------------------------------------------------------------
__global__ __launch_bounds__(THREADS, 2)
void hyper_logits_kernel(const float* __restrict__ inp,
                         const float* __restrict__ p,
                         const float* __restrict__ a,
                         float* __restrict__ out) {
    __shared__ __align__(16) float xs[2][BM][DTP];
    __shared__ __align__(16) float ps[2][BN][DTP];
    __shared__ __align__(16) float as_[2][BN][DTP];

    const int tid = threadIdx.x;
    const int kl = tid & 15;        // 0..15 : local k (handles kl and kl+16)
    const int bg = tid >> 4;        // 0..7  : group of 4 b's
    const int kbase = blockIdx.x * BN;
    const int bbase = blockIdx.y * BM;

    float accp[4][2] = {};          // <x_b, p_k>
    float acca[4][2] = {};          // <x_b, a_k>

    // ---- copy one DT-stage into buffer s (all 3 tiles) ----
    // Each tile is BM x DT floats = 256 float4; 128 threads -> 2 iters/tile.
    auto copy_stage = [&](int s, int d0) {
#pragma unroll
        for (int i = 0; i < 2; i++) {
            int idx = tid + i * 128;        // 0..255
            int row = idx >> 3;             // 0..31
            int c4  = (idx & 7) * 4;        // float col (f4 granularity)
            cp16(&xs[s][row][c4],  inp + (bbase + row) * D_DIM + d0 + c4);
            cp16(&ps[s][row][c4],  p   + (kbase + row) * D_DIM + d0 + c4);
            cp16(&as_[s][row][c4], a   + (kbase + row) * D_DIM + d0 + c4);
        }
    };

    // ---- pipeline ----
    copy_stage(0, 0);
    cp_commit();

    for (int t = 0; t < NSTAGE; t++) {
        if (t + 1 < NSTAGE) {
            copy_stage((t + 1) & 1, (t + 1) * DT);
            cp_commit();
            cp_wait1();         // stage t complete
        } else {
            cp_wait0();
        }
        __syncthreads();

        const int s = t & 1;
#pragma unroll
        for (int dc = 0; dc < DT / 4; dc++) {
            float4 xv[4], pv[2], av[2];
#pragma unroll
            for (int i = 0; i < 4; i++)
                xv[i] = *(const float4*)&xs[s][bg * 4 + i][dc * 4];
#pragma unroll
            for (int j = 0; j < 2; j++) {
                pv[j] = *(const float4*)&ps[s][kl + 16 * j][dc * 4];
                av[j] = *(const float4*)&as_[s][kl + 16 * j][dc * 4];
            }
#pragma unroll
            for (int i = 0; i < 4; i++) {
#pragma unroll
                for (int j = 0; j < 2; j++) {
                    accp[i][j] += xv[i].x * pv[j].x;
                    accp[i][j] += xv[i].y * pv[j].y;
                    accp[i][j] += xv[i].z * pv[j].z;
                    accp[i][j] += xv[i].w * pv[j].w;
                    acca[i][j] += xv[i].x * av[j].x;
                    acca[i][j] += xv[i].y * av[j].y;
                    acca[i][j] += xv[i].z * av[j].z;
                    acca[i][j] += xv[i].w * av[j].w;
                }
            }
        }
        __syncthreads();
    }

    // ---- Epilogue (c = 1, sqrt(c) = 1) ----
#pragma unroll
    for (int j = 0; j < 2; j++) {
        const int k = kbase + kl + 16 * j;
        const float uu = g_uu[k];
        const float ua = g_ua[k];
        const float anorm = sqrtf(g_a2[k]);
        const float lam = 2.0f / (1.0f - uu);
        const float coef = lam * anorm;
        const float beta = 1.0f - uu;
#pragma unroll
        for (int i = 0; i < 4; i++) {
            const int b = bbase + bg * 4 + i;
            float vv = g_vv[b];
            float uv = -accp[i][j];                       // <u, x> = -<p, x>
            float alpha = 1.0f + 2.0f * uv + vv;
            float den   = 1.0f + 2.0f * uv + uu * vv;
            float inv_den = 1.0f / den;
            float wa = (alpha * ua + beta * acca[i][j]) * inv_den;
            float ww = (alpha * alpha * uu + 2.0f * alpha * beta * uv
                        + beta * beta * vv) * (inv_den * inv_den);
            float num   = 2.0f * wa;
            float denom = anorm * (1.0f - ww);
            out[b * K_DIM + k] = coef * asinhf(num / denom);
        }
    }
}

// ---------------------------------------------------------------------------
extern "C" void kernel_launch(void* const* d_in, const int* in_sizes, int n_in,
                              void* d_out, int out_size) {
    const float* inp = (const float*)d_in[0];   // [B, D]
    const float* p   = (const float*)d_in[1];   // [K, D]
    const float* a   = (const float*)d_in[2];   // [K, D]
    float* out = (float*)d_out;                 // [B, K]

    // Kernel 1: (K + B) warps = 2176 warps -> 272 blocks of 256 threads
    int nwarps = K_DIM + B_DIM;
    int blocks1 = (nwarps * 32 + 255) / 256;
    stats_kernel<<<blocks1, 256>>>(inp, p, a);

    // Kernel 2: fused dual-GEMM + epilogue
    dim3 grid(K_DIM / BN, B_DIM / BM);   // (64, 4) = 256 blocks
    hyper_logits_kernel<<<grid, THREADS>>>(inp, p, a, out);
}